// round 1
// baseline (speedup 1.0000x reference)
#include <cuda_runtime.h>
#include <cstdint>

#define B_  4096
#define T_  2048
#define HH  32

// ---------------- device globals (no allocations allowed) ----------------
__device__ int g_next;          // work-queue cursor
__device__ int g_cnt[T_];       // histogram / offsets for counting sort
__device__ int g_order[B_];     // sequence ids sorted by descending length

// ---------------- f32x2 / MUFU helpers ----------------
__device__ __forceinline__ unsigned long long ffma2(unsigned long long a,
                                                    unsigned long long b,
                                                    unsigned long long c) {
    unsigned long long d;
    asm("fma.rn.f32x2 %0, %1, %2, %3;" : "=l"(d) : "l"(a), "l"(b), "l"(c));
    return d;
}
__device__ __forceinline__ unsigned long long pk2(float lo, float hi) {
    unsigned long long r;
    asm("mov.b64 %0, {%1, %2};" : "=l"(r) : "f"(lo), "f"(hi));
    return r;
}
__device__ __forceinline__ float2 unpk(unsigned long long v) {
    float2 r;
    asm("mov.b64 {%0, %1}, %2;" : "=f"(r.x), "=f"(r.y) : "l"(v));
    return r;
}
__device__ __forceinline__ float ex2a(float x) {
    float r; asm("ex2.approx.f32 %0, %1;" : "=f"(r) : "f"(x)); return r;
}
__device__ __forceinline__ float rcpa(float x) {
    float r; asm("rcp.approx.f32 %0, %1;" : "=f"(r) : "f"(x)); return r;
}
#define LOG2E 1.4426950408889634f
__device__ __forceinline__ float sig_f(float x) {
    // 1/(1+exp(-x))  via EX2 + RCP (~1e-6 accurate)
    return rcpa(1.0f + ex2a(-LOG2E * x));
}
__device__ __forceinline__ float tanh_f(float x) {
    // 1 - 2/(exp(2x)+1)
    return fmaf(-2.0f, rcpa(1.0f + ex2a(2.0f * LOG2E * x)), 1.0f);
}

// ---------------- setup kernels: counting sort by descending length ----------------
__global__ void k_zero() {
    int i = blockIdx.x * blockDim.x + threadIdx.x;
    if (i < T_) g_cnt[i] = 0;
    if (i == 0) g_next = 0;
}
__global__ void k_hist(const int* __restrict__ lengths) {
    int b = blockIdx.x * blockDim.x + threadIdx.x;
    if (b < B_) atomicAdd(&g_cnt[T_ - lengths[b]], 1);   // key: descending length
}
__global__ void k_scan() {
    // exclusive scan of g_cnt[0..2047], 1024 threads, 2 elems each
    __shared__ int ps[1024];
    int tid = threadIdx.x;
    int a = g_cnt[2 * tid], b = g_cnt[2 * tid + 1];
    int s = a + b;
    ps[tid] = s;
    __syncthreads();
    for (int d = 1; d < 1024; d <<= 1) {
        int v = (tid >= d) ? ps[tid - d] : 0;
        __syncthreads();
        ps[tid] += v;
        __syncthreads();
    }
    int incl = ps[tid];
    int excl = incl - s;                 // exclusive prefix at element 2*tid
    g_cnt[2 * tid]     = excl;
    g_cnt[2 * tid + 1] = excl + a;
}
__global__ void k_scatter(const int* __restrict__ lengths) {
    int b = blockIdx.x * blockDim.x + threadIdx.x;
    if (b < B_) {
        int pos = atomicAdd(&g_cnt[T_ - lengths[b]], 1);
        g_order[pos] = b;
    }
}

// ---------------- main persistent LSTM kernel ----------------
// one warp == one sequence (from the work queue); lane l owns element l of h/c
// and gate rows {l, 32+l, 64+l, 96+l}.
__global__ __launch_bounds__(256, 3) void k_lstm(
    const float* __restrict__ x,      const int*   __restrict__ lengths,
    const float* __restrict__ w_ih,   const float* __restrict__ w_hh,
    const float* __restrict__ b_ih,   const float* __restrict__ b_hh,
    const float* __restrict__ fc_w,   const float* __restrict__ fc_b,
    const float* __restrict__ fc2_w,  const float* __restrict__ fc2_b,
    float* __restrict__ out)
{
    // packed recurrent weights: Wp[(g*8+q)*32 + l] = float4 of
    // w_hh[32g+l][4q .. 4q+3]  -> lane-contiguous float4 => conflict-free LDS.128
    __shared__ __align__(16) float4 Wp[1024];
    __shared__ __align__(16) float  hs[2][8][HH];   // double-buffered h per warp

    const int tid  = threadIdx.x;
    const int lane = tid & 31;
    const int wrp  = tid >> 5;

    for (int e = tid; e < 1024; e += blockDim.x) {
        int g = e >> 8, q = (e >> 5) & 7, l = e & 31;
        const float* wr = w_hh + (32 * g + l) * 32 + 4 * q;
        Wp[e] = make_float4(wr[0], wr[1], wr[2], wr[3]);
    }
    __syncthreads();

    // per-lane gate constants
    float wih[4], bias[4];
#pragma unroll
    for (int g = 0; g < 4; g++) {
        int j = 32 * g + lane;
        wih[g]  = w_ih[j];
        bias[g] = b_ih[j] + b_hh[j];
    }
    const ulonglong2* WpU = reinterpret_cast<const ulonglong2*>(Wp) + lane;

    for (;;) {
        int task = 0;
        if (lane == 0) task = atomicAdd(&g_next, 1);
        task = __shfl_sync(0xffffffffu, task, 0);
        if (task >= B_) break;

        const int b   = g_order[task];
        const int len = lengths[b];
        const float* xp = x + (long)b * T_;

        float c = 0.0f;
        hs[0][wrp][lane] = 0.0f;
        hs[1][wrp][lane] = 0.0f;
        __syncwarp();

        float xt = __ldg(xp + (len - 1));
        int pb = 0;   // buffer currently holding h (to be read)

        for (int t = len - 1; t >= 0; --t) {
            float xn = (t > 0) ? __ldg(xp + t - 1) : 0.0f;   // prefetch next x

            const ulonglong2* hp =
                reinterpret_cast<const ulonglong2*>(hs[pb][wrp]);

            unsigned long long acc0 = pk2(fmaf(xt, wih[0], bias[0]), 0.0f);
            unsigned long long acc1 = pk2(fmaf(xt, wih[1], bias[1]), 0.0f);
            unsigned long long acc2 = pk2(fmaf(xt, wih[2], bias[2]), 0.0f);
            unsigned long long acc3 = pk2(fmaf(xt, wih[3], bias[3]), 0.0f);

#pragma unroll
            for (int q = 0; q < 8; q++) {
                ulonglong2 h2 = hp[q];                       // broadcast LDS.128
                ulonglong2 w0 = WpU[(0 * 8 + q) * 32];
                ulonglong2 w1 = WpU[(1 * 8 + q) * 32];
                ulonglong2 w2 = WpU[(2 * 8 + q) * 32];
                ulonglong2 w3 = WpU[(3 * 8 + q) * 32];
                acc0 = ffma2(h2.x, w0.x, acc0); acc0 = ffma2(h2.y, w0.y, acc0);
                acc1 = ffma2(h2.x, w1.x, acc1); acc1 = ffma2(h2.y, w1.y, acc1);
                acc2 = ffma2(h2.x, w2.x, acc2); acc2 = ffma2(h2.y, w2.y, acc2);
                acc3 = ffma2(h2.x, w3.x, acc3); acc3 = ffma2(h2.y, w3.y, acc3);
            }
            float2 a0 = unpk(acc0), a1 = unpk(acc1), a2 = unpk(acc2), a3 = unpk(acc3);
            float gi = a0.x + a0.y;
            float gf = a1.x + a1.y;
            float gg = a2.x + a2.y;
            float go = a3.x + a3.y;

            float iv = sig_f(gi);
            float fv = sig_f(gf);
            float gv = tanh_f(gg);
            float ov = sig_f(go);
            c = fmaf(fv, c, iv * gv);
            float h = ov * tanh_f(c);

            pb ^= 1;
            hs[pb][wrp][lane] = h;
            __syncwarp();
            xt = xn;
        }

        // ---- MLP head: elu(h @ fc_w.T + fc_b) @ fc2_w.T + fc2_b -> sigmoid ----
        const float* hf = hs[pb][wrp];
        float y0 = fc_b[lane];
        float y1 = fc_b[lane + 32];
#pragma unroll
        for (int k = 0; k < 32; k++) {
            float hk = hf[k];
            y0 = fmaf(hk, __ldg(fc_w + lane * 32 + k),        y0);
            y1 = fmaf(hk, __ldg(fc_w + (lane + 32) * 32 + k), y1);
        }
        float e0 = (y0 > 0.0f) ? y0 : (ex2a(LOG2E * y0) - 1.0f);
        float e1 = (y1 > 0.0f) ? y1 : (ex2a(LOG2E * y1) - 1.0f);
        float p  = fmaf(e0, __ldg(fc2_w + lane),
                        e1 * __ldg(fc2_w + lane + 32));
#pragma unroll
        for (int off = 16; off; off >>= 1)
            p += __shfl_xor_sync(0xffffffffu, p, off);
        if (lane == 0) out[b] = sig_f(p + fc2_b[0]);
        __syncwarp();   // protect hs reuse by next task
    }
}

// ---------------- launch ----------------
extern "C" void kernel_launch(void* const* d_in, const int* in_sizes, int n_in,
                              void* d_out, int out_size)
{
    const float* x       = (const float*)d_in[0];
    const int*   lengths = (const int*)  d_in[1];
    const float* w_ih    = (const float*)d_in[2];
    const float* w_hh    = (const float*)d_in[3];
    const float* b_ih    = (const float*)d_in[4];
    const float* b_hh    = (const float*)d_in[5];
    const float* fc_w    = (const float*)d_in[6];
    const float* fc_b    = (const float*)d_in[7];
    const float* fc2_w   = (const float*)d_in[8];
    const float* fc2_b   = (const float*)d_in[9];
    float* out = (float*)d_out;

    k_zero<<<2, 1024>>>();
    k_hist<<<B_ / 256, 256>>>(lengths);
    k_scan<<<1, 1024>>>();
    k_scatter<<<B_ / 256, 256>>>(lengths);
    k_lstm<<<148 * 3, 256>>>(x, lengths, w_ih, w_hh, b_ih, b_hh,
                             fc_w, fc_b, fc2_w, fc2_b, out);
}